// round 12
// baseline (speedup 1.0000x reference)
#include <cuda_runtime.h>
#include <cuda_fp16.h>
#include <stdint.h>

#define H_ 8
#define DMODEL 512
#define DK_ 64
#define NB 4
#define LMAX 2048

// ---------------- scratch (fp16) ----------------
__device__ __half g_qh[NB * LMAX * DMODEL];
__device__ __half g_kh[NB * LMAX * DMODEL];
__device__ __half g_vh[NB * LMAX * DMODEL];
__device__ __half g_q[NB * LMAX * DMODEL];    // Q pre-scaled by log2e/8
__device__ __half g_k[NB * LMAX * DMODEL];
__device__ __half g_v[NB * LMAX * DMODEL];    // V TRANSPOSED [(b*512+d)][tok]
__device__ __half g_o[NB * LMAX * DMODEL];
__device__ __half g_w[4 * DMODEL * DMODEL];

// ---------------- helpers ----------------
__device__ __forceinline__ void mma_f16(float* d, const unsigned* a, unsigned b0, unsigned b1) {
    asm volatile(
        "mma.sync.aligned.m16n8k16.row.col.f32.f16.f16.f32 "
        "{%0,%1,%2,%3},{%4,%5,%6,%7},{%8,%9},{%0,%1,%2,%3};"
        : "+f"(d[0]), "+f"(d[1]), "+f"(d[2]), "+f"(d[3])
        : "r"(a[0]), "r"(a[1]), "r"(a[2]), "r"(a[3]), "r"(b0), "r"(b1));
}
__device__ __forceinline__ void ldsm4(unsigned& r0, unsigned& r1, unsigned& r2, unsigned& r3,
                                      uint32_t addr) {
    asm volatile("ldmatrix.sync.aligned.m8n8.x4.shared.b16 {%0,%1,%2,%3}, [%4];"
                 : "=r"(r0), "=r"(r1), "=r"(r2), "=r"(r3) : "r"(addr));
}
__device__ __forceinline__ float ex2(float x) {
    float y; asm("ex2.approx.ftz.f32 %0, %1;" : "=f"(y) : "f"(x)); return y;
}
__device__ __forceinline__ void cp16(uint32_t dst, const void* src) {
    asm volatile("cp.async.cg.shared.global [%0], [%1], 16;" :: "r"(dst), "l"(src));
}
__device__ __forceinline__ unsigned pack_h2(float a, float b) {
    __half2 h = __floats2half2_rn(a, b);
    return *(unsigned*)&h;
}
__device__ __forceinline__ unsigned hmul2(unsigned a, unsigned b) {
    unsigned r;
    asm("mul.f16x2 %0, %1, %2;" : "=r"(r) : "r"(a), "r"(b));
    return r;
}
#define CP_COMMIT asm volatile("cp.async.commit_group;")
#define CP_WAIT1  asm volatile("cp.async.wait_group 1;")
#define CP_WAIT0  asm volatile("cp.async.wait_group 0;")

// ================= merged prepass: fp32 -> fp16 (inputs + weights) ========
__global__ void __launch_bounds__(256) cvt_all(
    const float* __restrict__ s0, const float* __restrict__ s1, const float* __restrict__ s2,
    const float* __restrict__ w0, const float* __restrict__ w1,
    const float* __restrict__ w2, const float* __restrict__ w3,
    __half* __restrict__ d0, __half* __restrict__ d1, __half* __restrict__ d2,
    __half* __restrict__ dw, int n4_in, int n4_w)
{
    const int z = blockIdx.z;
    const float4* s;
    uint2* d;
    int n4;
    if (z < 3) {
        s  = (const float4*)((z == 0) ? s0 : (z == 1) ? s1 : s2);
        d  = (uint2*)((z == 0) ? d0 : (z == 1) ? d1 : d2);
        n4 = n4_in;
    } else {
        const int zw = z - 3;
        s  = (const float4*)((zw == 0) ? w0 : (zw == 1) ? w1 : (zw == 2) ? w2 : w3);
        d  = (uint2*)(dw + (size_t)zw * DMODEL * DMODEL);
        n4 = n4_w;
    }
    for (int i = blockIdx.x * 256 + threadIdx.x; i < n4; i += gridDim.x * 256) {
        float4 v = s[i];
        d[i] = make_uint2(pack_h2(v.x, v.y), pack_h2(v.z, v.w));
    }
}

// ================= fp16 NT GEMM (fused 3-way), 3-stage, k-tile 64 =========
#define GSTG3 32768

__global__ void __launch_bounds__(256, 2) gemm3_f16(
    const __half* __restrict__ A0, const __half* __restrict__ A1, const __half* __restrict__ A2,
    const __half* __restrict__ Wt, int w_off,
    const float* __restrict__ B0, const float* __restrict__ B1, const float* __restrict__ B2,
    __half* __restrict__ C0, __half* __restrict__ C1, __half* __restrict__ C2,
    float* __restrict__ Cf,
    int M, int N, int K, int out_f16, int Lpar, int vt_mode, float q_scale)
{
    extern __shared__ char smc[];
    const uint32_t smb = (uint32_t)__cvta_generic_to_shared(smc);

    const int z = blockIdx.z;
    const __half* A    = (z == 0) ? A0 : (z == 1) ? A1 : A2;
    const __half* W    = Wt + (size_t)(w_off + z) * DMODEL * DMODEL;
    const float*  bias = (z == 0) ? B0 : (z == 1) ? B1 : B2;
    __half*       Ch   = (z == 0) ? C0 : (z == 1) ? C1 : C2;
    const bool    vt   = (z == 2) && vt_mode;
    const float   osc  = (z == 0) ? q_scale : 1.0f;

    const int tid  = threadIdx.x;
    const int lane = tid & 31;
    const int warp = tid >> 5;
    const int g = lane >> 2;
    const int t = lane & 3;
    const int wm = warp >> 1;
    const int wn = warp & 1;
    const int m0 = blockIdx.y * 128;
    const int n0 = blockIdx.x * 128;

    const int grow = tid >> 1;
    const int cb0  = (tid & 1) * 4;
    const __half* Ap = A + (size_t)(m0 + grow) * K;
    const __half* Wp = W + (size_t)(n0 + grow) * K;
    const int xr = grow & 7;
    const uint32_t arow = smb + grow * 128;
    const uint32_t brow = smb + 16384 + grow * 128;

    const int frow = lane & 15;
    const int fhi  = lane >> 4;
    const int fx   = lane & 7;
    int cbk[4];
#pragma unroll
    for (int ks = 0; ks < 4; ks++) cbk[ks] = ((2 * ks + fhi) ^ fx) * 16;
    uint32_t a_rt[2], b_rt[4];
#pragma unroll
    for (int mt = 0; mt < 2; mt++) a_rt[mt] = (wm * 32 + mt * 16 + frow) * 128;
#pragma unroll
    for (int p = 0; p < 4; p++)    b_rt[p] = 16384 + (wn * 64 + p * 16 + frow) * 128;

    float acc[2][8][4] = {};
    const int nK = K / 64;

#define G_ISSUE(it) do {                                                   \
        const uint32_t so_ = ((it) % 3) * GSTG3;                          \
        const int k0_ = (it) * 64;                                        \
        _Pragma("unroll")                                                  \
        for (int j = 0; j < 4; j++) {                                     \
            const int c_ = cb0 + j;                                       \
            cp16(arow + so_ + ((c_ ^ xr) * 16), Ap + k0_ + c_ * 8);       \
            cp16(brow + so_ + ((c_ ^ xr) * 16), Wp + k0_ + c_ * 8);       \
        }                                                                  \
    } while (0)

    G_ISSUE(0); CP_COMMIT;
    G_ISSUE(1); CP_COMMIT;

    for (int it = 0; it < nK; it++) {
        if (it + 1 < nK) { CP_WAIT1; } else { CP_WAIT0; }
        __syncthreads();

        const uint32_t base = smb + (it % 3) * GSTG3;
#pragma unroll
        for (int ks = 0; ks < 4; ks++) {
            unsigned a[2][4], bf[4][4];
#pragma unroll
            for (int mt = 0; mt < 2; mt++)
                ldsm4(a[mt][0], a[mt][1], a[mt][2], a[mt][3], base + a_rt[mt] + cbk[ks]);
#pragma unroll
            for (int p = 0; p < 4; p++)
                ldsm4(bf[p][0], bf[p][1], bf[p][2], bf[p][3], base + b_rt[p] + cbk[ks]);
#pragma unroll
            for (int mt = 0; mt < 2; mt++)
#pragma unroll
                for (int p = 0; p < 4; p++) {
                    mma_f16(acc[mt][2 * p],     a[mt], bf[p][0], bf[p][2]);
                    mma_f16(acc[mt][2 * p + 1], a[mt], bf[p][1], bf[p][3]);
                }
        }
        if (it + 2 < nK) { G_ISSUE(it + 2); CP_COMMIT; }
    }

#pragma unroll
    for (int mt = 0; mt < 2; mt++) {
        const int row0 = m0 + wm * 32 + mt * 16 + g;
#pragma unroll
        for (int nt = 0; nt < 8; nt++) {
            const int col = n0 + wn * 64 + nt * 8 + 2 * t;
            const float b0 = bias[col], b1 = bias[col + 1];
            const float v00 = (acc[mt][nt][0] + b0) * osc, v01 = (acc[mt][nt][1] + b1) * osc;
            const float v10 = (acc[mt][nt][2] + b0) * osc, v11 = (acc[mt][nt][3] + b1) * osc;
            if (!out_f16) {
                *(float2*)&Cf[(size_t)row0 * N + col]       = make_float2(v00, v01);
                *(float2*)&Cf[(size_t)(row0 + 8) * N + col] = make_float2(v10, v11);
            } else if (vt) {
                const int bI  = row0 / Lpar;
                const int tok = row0 - bI * Lpar;
                __half* base0 = Ch + (size_t)(bI * DMODEL + col) * Lpar;
                __half* base1 = base0 + Lpar;
                base0[tok]     = __float2half_rn(v00);
                base1[tok]     = __float2half_rn(v01);
                base0[tok + 8] = __float2half_rn(v10);
                base1[tok + 8] = __float2half_rn(v11);
            } else {
                *(unsigned*)&Ch[(size_t)row0 * N + col]       = pack_h2(v00, v01);
                *(unsigned*)&Ch[(size_t)(row0 + 8) * N + col] = pack_h2(v10, v11);
            }
        }
    }
}

// ================= flash attention: 4-warp CTAs, 4 CTAs/SM ================
// Bq=64, 4 warps x 16 q-rows. 2-stage K/V ring (second barrier guards reuse).
// smem: K[2][8192] | V[2][8192] | P[8192] | msk2[4096] = 45056 B
#define AKS2 8192
#define ONES2 0x3C003C00u

__global__ void __launch_bounds__(128, 4) attn_f16(
    const __half* __restrict__ Qb, const __half* __restrict__ Kb,
    const __half* __restrict__ Vt, const int* __restrict__ mask,
    __half* __restrict__ Ob, int L)
{
    extern __shared__ char smc[];
    const uint32_t smb = (uint32_t)__cvta_generic_to_shared(smc);
    const uint32_t smP = smb + 4 * AKS2;                  // 32768
    unsigned* msk2 = (unsigned*)(smc + 4 * AKS2 + 8192);  // 40960

    const int b  = blockIdx.z;
    const int h  = blockIdx.y;
    const int q0 = blockIdx.x * 64;

    const int tid  = threadIdx.x;
    const int lane = tid & 31;
    const int warp = tid >> 5;          // 0..3
    const int g = lane >> 2;
    const int t = lane & 3;
    const int wr0 = warp * 16;

    // mask -> half2 {1,0} table + "any zero" detection
    int bad = 0;
    {
        const int2* m2 = (const int2*)(mask + (size_t)b * L);
        for (int i = tid; i < L / 2; i += 128) {
            int2 mm = m2[i];
            msk2[i] = (mm.x ? 0x3C00u : 0u) | (mm.y ? 0x3C000000u : 0u);
            bad |= (mm.x == 0) | (mm.y == 0);
        }
    }
    const int use_mask = __syncthreads_or(bad);   // also orders msk2 writes

    // Q fragments (pre-scaled by log2e/8 at projection)
    unsigned qa[4][4];
    {
        const __half* q_r0 = Qb + ((size_t)b * L + q0 + wr0 + g) * DMODEL + h * DK_;
        const __half* q_r1 = q_r0 + 8 * DMODEL;
#pragma unroll
        for (int ks = 0; ks < 4; ks++) {
            qa[ks][0] = *(const unsigned*)&q_r0[16 * ks + 2 * t];
            qa[ks][1] = *(const unsigned*)&q_r1[16 * ks + 2 * t];
            qa[ks][2] = *(const unsigned*)&q_r0[16 * ks + 8 + 2 * t];
            qa[ks][3] = *(const unsigned*)&q_r1[16 * ks + 8 + 2 * t];
        }
    }

    float o[8][4] = {};
    float lacc[4] = {};   // row-sum accumulator via ones-mma

    const int frow = lane & 15;
    const int fhi  = lane >> 4;
    const int fx   = lane & 7;
    uint32_t kvrow[4];
#pragma unroll
    for (int p = 0; p < 4; p++) kvrow[p] = (p * 16 + frow) * 128;
    const uint32_t prow = smP + (wr0 + frow) * 128;
    int cb[4];
#pragma unroll
    for (int ks = 0; ks < 4; ks++) cb[ks] = ((2 * ks + fhi) ^ fx) * 16;

    const uint32_t pr0 = smP + (wr0 + g) * 128;
    const uint32_t pr1 = pr0 + 8 * 128;
    const int gx = g & 7;

    // cp.async: 128 threads, 2 per row; 4 K-chunks + 4 V-chunks per thread
    const int lr = tid >> 1;            // 0..63
    const int c0 = (tid & 1) * 4;

#define A_ISSUE(it) do {                                                         \
        const uint32_t so_ = ((it) & 1) * AKS2;                                 \
        const int k0_ = (it) * 64;                                              \
        const __half* kp_ = Kb + ((size_t)b * L + k0_ + lr) * DMODEL + h * DK_; \
        const __half* vp_ = Vt + ((size_t)(b * DMODEL + h * DK_ + lr)) * L + k0_;\
        const uint32_t kd_ = smb + so_ + lr * 128;                              \
        const uint32_t vd_ = smb + 2 * AKS2 + so_ + lr * 128;                   \
        const int xw_ = lr & 7;                                                 \
        _Pragma("unroll")                                                        \
        for (int j = 0; j < 4; j++) {                                           \
            const int c_ = c0 + j;                                              \
            cp16(kd_ + ((c_ ^ xw_) * 16), kp_ + c_ * 8);                        \
            cp16(vd_ + ((c_ ^ xw_) * 16), vp_ + c_ * 8);                        \
        }                                                                        \
    } while (0)

    const int nT = L / 64;
    A_ISSUE(0); CP_COMMIT;
    A_ISSUE(1); CP_COMMIT;

    for (int it = 0; it < nT; it++) {
        if (it + 1 < nT) { CP_WAIT1; } else { CP_WAIT0; }
        __syncthreads();

        const uint32_t smK = smb + (it & 1) * AKS2;
        const uint32_t smV = smb + 2 * AKS2 + (it & 1) * AKS2;
        const int k0 = it * 64;

        // ---- S = Q K^T (pre-scaled; exp2 domain) ----
        float s[8][4];
#pragma unroll
        for (int nt = 0; nt < 8; nt++) s[nt][0] = s[nt][1] = s[nt][2] = s[nt][3] = 0.f;
#pragma unroll
        for (int ks = 0; ks < 4; ks++) {
            unsigned kf[4][4];
#pragma unroll
            for (int p = 0; p < 4; p++)
                ldsm4(kf[p][0], kf[p][1], kf[p][2], kf[p][3], smK + kvrow[p] + cb[ks]);
#pragma unroll
            for (int p = 0; p < 4; p++) {
                mma_f16(s[2 * p],     qa[ks], kf[p][0], kf[p][2]);
                mma_f16(s[2 * p + 1], qa[ks], kf[p][1], kf[p][3]);
            }
        }

        // ---- P = [mask *] exp2(S); store to smem ----
        __syncwarp();   // WAR vs previous PV ldsm of P
#pragma unroll
        for (int nt = 0; nt < 8; nt++) {
            unsigned lo = pack_h2(ex2(s[nt][0]), ex2(s[nt][1]));
            unsigned hi = pack_h2(ex2(s[nt][2]), ex2(s[nt][3]));
            if (use_mask) {
                const unsigned mk = msk2[(k0 + nt * 8) / 2 + t];
                lo = hmul2(lo, mk);
                hi = hmul2(hi, mk);
            }
            const int byt = ((nt ^ gx) << 4) + 4 * t;
            asm volatile("st.shared.u32 [%0], %1;" :: "r"(pr0 + byt), "r"(lo));
            asm volatile("st.shared.u32 [%0], %1;" :: "r"(pr1 + byt), "r"(hi));
        }
        __syncwarp();

        // ---- O += P @ V ; l += P @ 1 ----
#pragma unroll
        for (int ks = 0; ks < 4; ks++) {
            unsigned pa[4];
            ldsm4(pa[0], pa[1], pa[2], pa[3], prow + cb[ks]);
            unsigned vf[4][4];
#pragma unroll
            for (int p = 0; p < 4; p++)
                ldsm4(vf[p][0], vf[p][1], vf[p][2], vf[p][3], smV + kvrow[p] + cb[ks]);
#pragma unroll
            for (int p = 0; p < 4; p++) {
                mma_f16(o[2 * p],     pa, vf[p][0], vf[p][2]);
                mma_f16(o[2 * p + 1], pa, vf[p][1], vf[p][3]);
            }
            mma_f16(lacc, pa, ONES2, ONES2);
        }

        __syncthreads();   // stage (it&1) free for reuse
        if (it + 2 < nT) { A_ISSUE(it + 2); CP_COMMIT; }
    }

    const float inv0 = 1.f / lacc[0];
    const float inv1 = 1.f / lacc[2];
    __half* o_r0 = Ob + ((size_t)b * L + q0 + wr0 + g) * DMODEL + h * DK_;
    __half* o_r1 = o_r0 + 8 * DMODEL;
#pragma unroll
    for (int dt = 0; dt < 8; dt++) {
        *(unsigned*)&o_r0[dt * 8 + 2 * t] = pack_h2(o[dt][0] * inv0, o[dt][1] * inv0);
        *(unsigned*)&o_r1[dt * 8 + 2 * t] = pack_h2(o[dt][2] * inv1, o[dt][3] * inv1);
    }
}

// ---------------- launch ----------------
extern "C" void kernel_launch(void* const* d_in, const int* in_sizes, int n_in,
                              void* d_out, int out_size)
{
    const float* query = (const float*)d_in[0];
    const float* key   = (const float*)d_in[1];
    const float* value = (const float*)d_in[2];
    const int*   mask  = (const int*)d_in[3];
    const float* Wq = (const float*)d_in[4];
    const float* bq = (const float*)d_in[5];
    const float* Wk = (const float*)d_in[6];
    const float* bk = (const float*)d_in[7];
    const float* Wv = (const float*)d_in[8];
    const float* bv = (const float*)d_in[9];
    const float* Wo = (const float*)d_in[10];
    const float* bo = (const float*)d_in[11];

    const int N = NB;
    const int L = in_sizes[3] / N;
    const int M = N * L;

    __half *qh, *kh, *vh, *qb, *kb, *vb, *ob, *wb;
    cudaGetSymbolAddress((void**)&qh, g_qh);
    cudaGetSymbolAddress((void**)&kh, g_kh);
    cudaGetSymbolAddress((void**)&vh, g_vh);
    cudaGetSymbolAddress((void**)&qb, g_q);
    cudaGetSymbolAddress((void**)&kb, g_k);
    cudaGetSymbolAddress((void**)&vb, g_v);
    cudaGetSymbolAddress((void**)&ob, g_o);
    cudaGetSymbolAddress((void**)&wb, g_w);

    const int n4_in = M * DMODEL / 4;
    const int n4_w  = DMODEL * DMODEL / 4;
    cvt_all<<<dim3(512, 1, 7), 256>>>(query, key, value, Wq, Wk, Wv, Wo,
                                      qh, kh, vh, wb, n4_in, n4_w);

    const int gemm_smem = 3 * GSTG3;   // 98304 B
    cudaFuncSetAttribute(gemm3_f16, cudaFuncAttributeMaxDynamicSharedMemorySize, gemm_smem);

    const float SC = 0.18033688f;   // (1/sqrt(64)) * log2(e) folded into Q
    gemm3_f16<<<dim3(DMODEL / 128, M / 128, 3), 256, gemm_smem>>>(
        qh, kh, vh, wb, 0, bq, bk, bv, qb, kb, vb, nullptr,
        M, DMODEL, DMODEL, 1, L, 1, SC);

    const int attn_smem = 4 * AKS2 + 8192 + 4096;   // 45056 B
    cudaFuncSetAttribute(attn_f16, cudaFuncAttributeMaxDynamicSharedMemorySize, attn_smem);
    attn_f16<<<dim3(L / 64, H_, N), 128, attn_smem>>>(qb, kb, vb, mask, ob, L);

    gemm3_f16<<<dim3(DMODEL / 128, M / 128, 1), 256, gemm_smem>>>(
        ob, ob, ob, wb, 3, bo, bo, bo, nullptr, nullptr, nullptr, (float*)d_out,
        M, DMODEL, DMODEL, 0, L, 0, 1.0f);
}

// round 13
// speedup vs baseline: 1.0983x; 1.0983x over previous
#include <cuda_runtime.h>
#include <cuda_fp16.h>
#include <stdint.h>

#define H_ 8
#define DMODEL 512
#define DK_ 64
#define NB 4
#define LMAX 2048

// ---------------- scratch (fp16) ----------------
__device__ __half g_qh[NB * LMAX * DMODEL];
__device__ __half g_kh[NB * LMAX * DMODEL];
__device__ __half g_vh[NB * LMAX * DMODEL];
__device__ __half g_q[NB * LMAX * DMODEL];    // Q pre-scaled by log2e/8
__device__ __half g_k[NB * LMAX * DMODEL];
__device__ __half g_v[NB * LMAX * DMODEL];    // V TRANSPOSED [(b*512+d)][tok]
__device__ __half g_o[NB * LMAX * DMODEL];
__device__ __half g_w[4 * DMODEL * DMODEL];

// ---------------- helpers ----------------
__device__ __forceinline__ void mma_f16(float* d, const unsigned* a, unsigned b0, unsigned b1) {
    asm volatile(
        "mma.sync.aligned.m16n8k16.row.col.f32.f16.f16.f32 "
        "{%0,%1,%2,%3},{%4,%5,%6,%7},{%8,%9},{%0,%1,%2,%3};"
        : "+f"(d[0]), "+f"(d[1]), "+f"(d[2]), "+f"(d[3])
        : "r"(a[0]), "r"(a[1]), "r"(a[2]), "r"(a[3]), "r"(b0), "r"(b1));
}
__device__ __forceinline__ void ldsm4(unsigned& r0, unsigned& r1, unsigned& r2, unsigned& r3,
                                      uint32_t addr) {
    asm volatile("ldmatrix.sync.aligned.m8n8.x4.shared.b16 {%0,%1,%2,%3}, [%4];"
                 : "=r"(r0), "=r"(r1), "=r"(r2), "=r"(r3) : "r"(addr));
}
__device__ __forceinline__ void cp16(uint32_t dst, const void* src) {
    asm volatile("cp.async.cg.shared.global [%0], [%1], 16;" :: "r"(dst), "l"(src));
}
__device__ __forceinline__ unsigned pack_h2(float a, float b) {
    __half2 h = __floats2half2_rn(a, b);
    return *(unsigned*)&h;
}
__device__ __forceinline__ unsigned ex2_h2(unsigned x) {
    unsigned r;
    asm("ex2.approx.f16x2 %0, %1;" : "=r"(r) : "r"(x));
    return r;
}
__device__ __forceinline__ unsigned hmul2(unsigned a, unsigned b) {
    unsigned r;
    asm("mul.f16x2 %0, %1, %2;" : "=r"(r) : "r"(a), "r"(b));
    return r;
}
#define CP_COMMIT asm volatile("cp.async.commit_group;")
#define CP_WAIT1  asm volatile("cp.async.wait_group 1;")
#define CP_WAIT0  asm volatile("cp.async.wait_group 0;")

// ================= merged prepass: fp32 -> fp16 (inputs + weights) ========
__global__ void __launch_bounds__(256) cvt_all(
    const float* __restrict__ s0, const float* __restrict__ s1, const float* __restrict__ s2,
    const float* __restrict__ w0, const float* __restrict__ w1,
    const float* __restrict__ w2, const float* __restrict__ w3,
    __half* __restrict__ d0, __half* __restrict__ d1, __half* __restrict__ d2,
    __half* __restrict__ dw, int n4_in, int n4_w)
{
    const int z = blockIdx.z;
    const float4* s;
    uint2* d;
    int n4;
    if (z < 3) {
        s  = (const float4*)((z == 0) ? s0 : (z == 1) ? s1 : s2);
        d  = (uint2*)((z == 0) ? d0 : (z == 1) ? d1 : d2);
        n4 = n4_in;
    } else {
        const int zw = z - 3;
        s  = (const float4*)((zw == 0) ? w0 : (zw == 1) ? w1 : (zw == 2) ? w2 : w3);
        d  = (uint2*)(dw + (size_t)zw * DMODEL * DMODEL);
        n4 = n4_w;
    }
    for (int i = blockIdx.x * 256 + threadIdx.x; i < n4; i += gridDim.x * 256) {
        float4 v = s[i];
        d[i] = make_uint2(pack_h2(v.x, v.y), pack_h2(v.z, v.w));
    }
}

// ================= fp16 NT GEMM (fused 3-way), 3-stage, k-tile 64 =========
#define GSTG3 32768

__global__ void __launch_bounds__(256, 2) gemm3_f16(
    const __half* __restrict__ A0, const __half* __restrict__ A1, const __half* __restrict__ A2,
    const __half* __restrict__ Wt, int w_off,
    const float* __restrict__ B0, const float* __restrict__ B1, const float* __restrict__ B2,
    __half* __restrict__ C0, __half* __restrict__ C1, __half* __restrict__ C2,
    float* __restrict__ Cf,
    int M, int N, int K, int out_f16, int Lpar, int vt_mode, float q_scale)
{
    extern __shared__ char smc[];
    const uint32_t smb = (uint32_t)__cvta_generic_to_shared(smc);

    const int z = blockIdx.z;
    const __half* A    = (z == 0) ? A0 : (z == 1) ? A1 : A2;
    const __half* W    = Wt + (size_t)(w_off + z) * DMODEL * DMODEL;
    const float*  bias = (z == 0) ? B0 : (z == 1) ? B1 : B2;
    __half*       Ch   = (z == 0) ? C0 : (z == 1) ? C1 : C2;
    const bool    vt   = (z == 2) && vt_mode;
    const float   osc  = (z == 0) ? q_scale : 1.0f;

    const int tid  = threadIdx.x;
    const int lane = tid & 31;
    const int warp = tid >> 5;
    const int g = lane >> 2;
    const int t = lane & 3;
    const int wm = warp >> 1;
    const int wn = warp & 1;
    const int m0 = blockIdx.y * 128;
    const int n0 = blockIdx.x * 128;

    const int grow = tid >> 1;
    const int cb0  = (tid & 1) * 4;
    const __half* Ap = A + (size_t)(m0 + grow) * K;
    const __half* Wp = W + (size_t)(n0 + grow) * K;
    const int xr = grow & 7;
    const uint32_t arow = smb + grow * 128;
    const uint32_t brow = smb + 16384 + grow * 128;

    const int frow = lane & 15;
    const int fhi  = lane >> 4;
    const int fx   = lane & 7;
    int cbk[4];
#pragma unroll
    for (int ks = 0; ks < 4; ks++) cbk[ks] = ((2 * ks + fhi) ^ fx) * 16;
    uint32_t a_rt[2], b_rt[4];
#pragma unroll
    for (int mt = 0; mt < 2; mt++) a_rt[mt] = (wm * 32 + mt * 16 + frow) * 128;
#pragma unroll
    for (int p = 0; p < 4; p++)    b_rt[p] = 16384 + (wn * 64 + p * 16 + frow) * 128;

    float acc[2][8][4] = {};
    const int nK = K / 64;

#define G_ISSUE(it) do {                                                   \
        const uint32_t so_ = ((it) % 3) * GSTG3;                          \
        const int k0_ = (it) * 64;                                        \
        _Pragma("unroll")                                                  \
        for (int j = 0; j < 4; j++) {                                     \
            const int c_ = cb0 + j;                                       \
            cp16(arow + so_ + ((c_ ^ xr) * 16), Ap + k0_ + c_ * 8);       \
            cp16(brow + so_ + ((c_ ^ xr) * 16), Wp + k0_ + c_ * 8);       \
        }                                                                  \
    } while (0)

    G_ISSUE(0); CP_COMMIT;
    G_ISSUE(1); CP_COMMIT;

    for (int it = 0; it < nK; it++) {
        if (it + 1 < nK) { CP_WAIT1; } else { CP_WAIT0; }
        __syncthreads();

        const uint32_t base = smb + (it % 3) * GSTG3;
#pragma unroll
        for (int ks = 0; ks < 4; ks++) {
            unsigned a[2][4], bf[4][4];
#pragma unroll
            for (int mt = 0; mt < 2; mt++)
                ldsm4(a[mt][0], a[mt][1], a[mt][2], a[mt][3], base + a_rt[mt] + cbk[ks]);
#pragma unroll
            for (int p = 0; p < 4; p++)
                ldsm4(bf[p][0], bf[p][1], bf[p][2], bf[p][3], base + b_rt[p] + cbk[ks]);
#pragma unroll
            for (int mt = 0; mt < 2; mt++)
#pragma unroll
                for (int p = 0; p < 4; p++) {
                    mma_f16(acc[mt][2 * p],     a[mt], bf[p][0], bf[p][2]);
                    mma_f16(acc[mt][2 * p + 1], a[mt], bf[p][1], bf[p][3]);
                }
        }
        if (it + 2 < nK) { G_ISSUE(it + 2); CP_COMMIT; }
    }

#pragma unroll
    for (int mt = 0; mt < 2; mt++) {
        const int row0 = m0 + wm * 32 + mt * 16 + g;
#pragma unroll
        for (int nt = 0; nt < 8; nt++) {
            const int col = n0 + wn * 64 + nt * 8 + 2 * t;
            const float b0 = bias[col], b1 = bias[col + 1];
            const float v00 = (acc[mt][nt][0] + b0) * osc, v01 = (acc[mt][nt][1] + b1) * osc;
            const float v10 = (acc[mt][nt][2] + b0) * osc, v11 = (acc[mt][nt][3] + b1) * osc;
            if (!out_f16) {
                *(float2*)&Cf[(size_t)row0 * N + col]       = make_float2(v00, v01);
                *(float2*)&Cf[(size_t)(row0 + 8) * N + col] = make_float2(v10, v11);
            } else if (vt) {
                const int bI  = row0 / Lpar;
                const int tok = row0 - bI * Lpar;
                __half* base0 = Ch + (size_t)(bI * DMODEL + col) * Lpar;
                __half* base1 = base0 + Lpar;
                base0[tok]     = __float2half_rn(v00);
                base1[tok]     = __float2half_rn(v01);
                base0[tok + 8] = __float2half_rn(v10);
                base1[tok + 8] = __float2half_rn(v11);
            } else {
                *(unsigned*)&Ch[(size_t)row0 * N + col]       = pack_h2(v00, v01);
                *(unsigned*)&Ch[(size_t)(row0 + 8) * N + col] = pack_h2(v10, v11);
            }
        }
    }
}

// ================= flash attention (R11 shape + f16x2 exp) ================
// Bq=128, 8 warps, 3-stage K/V rings, 2 CTAs/SM.
// smem: K[3][8192] | V[3][8192] | P[16384] | msk2[4096] = 69632 B
#define AKS 8192
#define ONES2 0x3C003C00u

__global__ void __launch_bounds__(256, 2) attn_f16(
    const __half* __restrict__ Qb, const __half* __restrict__ Kb,
    const __half* __restrict__ Vt, const int* __restrict__ mask,
    __half* __restrict__ Ob, int L)
{
    extern __shared__ char smc[];
    const uint32_t smb = (uint32_t)__cvta_generic_to_shared(smc);
    const uint32_t smP = smb + 6 * AKS;
    unsigned* msk2 = (unsigned*)(smc + 6 * AKS + 16384);   // L/2 half2 entries

    const int b  = blockIdx.z;
    const int h  = blockIdx.y;
    const int q0 = blockIdx.x * 128;

    const int tid  = threadIdx.x;
    const int lane = tid & 31;
    const int warp = tid >> 5;
    const int g = lane >> 2;
    const int t = lane & 3;
    const int wr0 = warp * 16;

    // mask -> half2 {1,0} table + "any zero" detection
    int bad = 0;
    {
        const int2* m2 = (const int2*)(mask + (size_t)b * L);
        for (int i = tid; i < L / 2; i += 256) {
            int2 mm = m2[i];
            msk2[i] = (mm.x ? 0x3C00u : 0u) | (mm.y ? 0x3C000000u : 0u);
            bad |= (mm.x == 0) | (mm.y == 0);
        }
    }
    const int use_mask = __syncthreads_or(bad);   // also orders msk2 writes

    // Q fragments (pre-scaled by log2e/8 at projection)
    unsigned qa[4][4];
    {
        const __half* q_r0 = Qb + ((size_t)b * L + q0 + wr0 + g) * DMODEL + h * DK_;
        const __half* q_r1 = q_r0 + 8 * DMODEL;
#pragma unroll
        for (int ks = 0; ks < 4; ks++) {
            qa[ks][0] = *(const unsigned*)&q_r0[16 * ks + 2 * t];
            qa[ks][1] = *(const unsigned*)&q_r1[16 * ks + 2 * t];
            qa[ks][2] = *(const unsigned*)&q_r0[16 * ks + 8 + 2 * t];
            qa[ks][3] = *(const unsigned*)&q_r1[16 * ks + 8 + 2 * t];
        }
    }

    float o[8][4] = {};
    float lacc[4] = {};   // row-sum accumulator via ones-mma

    const int frow = lane & 15;
    const int fhi  = lane >> 4;
    const int fx   = lane & 7;
    uint32_t kvrow[4];
#pragma unroll
    for (int p = 0; p < 4; p++) kvrow[p] = (p * 16 + frow) * 128;
    const uint32_t prow = smP + (wr0 + frow) * 128;
    int cb[4];
#pragma unroll
    for (int ks = 0; ks < 4; ks++) cb[ks] = ((2 * ks + fhi) ^ fx) * 16;

    const uint32_t pr0 = smP + (wr0 + g) * 128;
    const uint32_t pr1 = pr0 + 8 * 128;
    const int gx = g & 7;

    const int lr = tid >> 2;
    const int c0 = (tid & 3) * 2;

#define A_ISSUE(it) do {                                                         \
        const uint32_t so_ = ((it) % 3) * AKS;                                  \
        const int k0_ = (it) * 64;                                              \
        const __half* kp_ = Kb + ((size_t)b * L + k0_ + lr) * DMODEL + h * DK_; \
        const __half* vp_ = Vt + ((size_t)(b * DMODEL + h * DK_ + lr)) * L + k0_;\
        const uint32_t kd_ = smb + so_ + lr * 128;                              \
        const uint32_t vd_ = smb + 3 * AKS + so_ + lr * 128;                    \
        const int xw_ = lr & 7;                                                 \
        _Pragma("unroll")                                                        \
        for (int j = 0; j < 2; j++) {                                           \
            const int c_ = c0 + j;                                              \
            cp16(kd_ + ((c_ ^ xw_) * 16), kp_ + c_ * 8);                        \
            cp16(vd_ + ((c_ ^ xw_) * 16), vp_ + c_ * 8);                        \
        }                                                                        \
    } while (0)

    const int nT = L / 64;
    A_ISSUE(0); CP_COMMIT;
    A_ISSUE(1); CP_COMMIT;

    for (int it = 0; it < nT; it++) {
        if (it + 1 < nT) { CP_WAIT1; } else { CP_WAIT0; }
        __syncthreads();

        const uint32_t smK = smb + (it % 3) * AKS;
        const uint32_t smV = smb + 3 * AKS + (it % 3) * AKS;
        const int k0 = it * 64;

        // ---- S = Q K^T (pre-scaled; exp2 domain) ----
        float s[8][4];
#pragma unroll
        for (int nt = 0; nt < 8; nt++) s[nt][0] = s[nt][1] = s[nt][2] = s[nt][3] = 0.f;
#pragma unroll
        for (int ks = 0; ks < 4; ks++) {
            unsigned kf[4][4];
#pragma unroll
            for (int p = 0; p < 4; p++)
                ldsm4(kf[p][0], kf[p][1], kf[p][2], kf[p][3], smK + kvrow[p] + cb[ks]);
#pragma unroll
            for (int p = 0; p < 4; p++) {
                mma_f16(s[2 * p],     qa[ks], kf[p][0], kf[p][2]);
                mma_f16(s[2 * p + 1], qa[ks], kf[p][1], kf[p][3]);
            }
        }

        // ---- P = [mask *] exp2_h2(S); store to smem ----
        __syncwarp();   // WAR vs previous PV ldsm of P
#pragma unroll
        for (int nt = 0; nt < 8; nt++) {
            unsigned lo = ex2_h2(pack_h2(s[nt][0], s[nt][1]));
            unsigned hi = ex2_h2(pack_h2(s[nt][2], s[nt][3]));
            if (use_mask) {
                const unsigned mk = msk2[(k0 + nt * 8) / 2 + t];
                lo = hmul2(lo, mk);
                hi = hmul2(hi, mk);
            }
            const int byt = ((nt ^ gx) << 4) + 4 * t;
            asm volatile("st.shared.u32 [%0], %1;" :: "r"(pr0 + byt), "r"(lo));
            asm volatile("st.shared.u32 [%0], %1;" :: "r"(pr1 + byt), "r"(hi));
        }
        __syncwarp();

        // ---- O += P @ V ; l += P @ 1 ----
#pragma unroll
        for (int ks = 0; ks < 4; ks++) {
            unsigned pa[4];
            ldsm4(pa[0], pa[1], pa[2], pa[3], prow + cb[ks]);
            unsigned vf[4][4];
#pragma unroll
            for (int p = 0; p < 4; p++)
                ldsm4(vf[p][0], vf[p][1], vf[p][2], vf[p][3], smV + kvrow[p] + cb[ks]);
#pragma unroll
            for (int p = 0; p < 4; p++) {
                mma_f16(o[2 * p],     pa, vf[p][0], vf[p][2]);
                mma_f16(o[2 * p + 1], pa, vf[p][1], vf[p][3]);
            }
            mma_f16(lacc, pa, ONES2, ONES2);
        }
        if (it + 2 < nT) { A_ISSUE(it + 2); CP_COMMIT; }
    }

    const float inv0 = 1.f / lacc[0];
    const float inv1 = 1.f / lacc[2];
    __half* o_r0 = Ob + ((size_t)b * L + q0 + wr0 + g) * DMODEL + h * DK_;
    __half* o_r1 = o_r0 + 8 * DMODEL;
#pragma unroll
    for (int dt = 0; dt < 8; dt++) {
        *(unsigned*)&o_r0[dt * 8 + 2 * t] = pack_h2(o[dt][0] * inv0, o[dt][1] * inv0);
        *(unsigned*)&o_r1[dt * 8 + 2 * t] = pack_h2(o[dt][2] * inv1, o[dt][3] * inv1);
    }
}

// ---------------- launch ----------------
extern "C" void kernel_launch(void* const* d_in, const int* in_sizes, int n_in,
                              void* d_out, int out_size)
{
    const float* query = (const float*)d_in[0];
    const float* key   = (const float*)d_in[1];
    const float* value = (const float*)d_in[2];
    const int*   mask  = (const int*)d_in[3];
    const float* Wq = (const float*)d_in[4];
    const float* bq = (const float*)d_in[5];
    const float* Wk = (const float*)d_in[6];
    const float* bk = (const float*)d_in[7];
    const float* Wv = (const float*)d_in[8];
    const float* bv = (const float*)d_in[9];
    const float* Wo = (const float*)d_in[10];
    const float* bo = (const float*)d_in[11];

    const int N = NB;
    const int L = in_sizes[3] / N;
    const int M = N * L;

    __half *qh, *kh, *vh, *qb, *kb, *vb, *ob, *wb;
    cudaGetSymbolAddress((void**)&qh, g_qh);
    cudaGetSymbolAddress((void**)&kh, g_kh);
    cudaGetSymbolAddress((void**)&vh, g_vh);
    cudaGetSymbolAddress((void**)&qb, g_q);
    cudaGetSymbolAddress((void**)&kb, g_k);
    cudaGetSymbolAddress((void**)&vb, g_v);
    cudaGetSymbolAddress((void**)&ob, g_o);
    cudaGetSymbolAddress((void**)&wb, g_w);

    const int n4_in = M * DMODEL / 4;
    const int n4_w  = DMODEL * DMODEL / 4;
    cvt_all<<<dim3(512, 1, 7), 256>>>(query, key, value, Wq, Wk, Wv, Wo,
                                      qh, kh, vh, wb, n4_in, n4_w);

    const int gemm_smem = 3 * GSTG3;   // 98304 B
    cudaFuncSetAttribute(gemm3_f16, cudaFuncAttributeMaxDynamicSharedMemorySize, gemm_smem);

    const float SC = 0.18033688f;   // (1/sqrt(64)) * log2(e) folded into Q
    gemm3_f16<<<dim3(DMODEL / 128, M / 128, 3), 256, gemm_smem>>>(
        qh, kh, vh, wb, 0, bq, bk, bv, qb, kb, vb, nullptr,
        M, DMODEL, DMODEL, 1, L, 1, SC);

    const int attn_smem = 6 * AKS + 16384 + 4096;   // 69632 B
    cudaFuncSetAttribute(attn_f16, cudaFuncAttributeMaxDynamicSharedMemorySize, attn_smem);
    attn_f16<<<dim3(L / 128, H_, N), 256, attn_smem>>>(qb, kb, vb, mask, ob, L);

    gemm3_f16<<<dim3(DMODEL / 128, M / 128, 1), 256, gemm_smem>>>(
        ob, ob, ob, wb, 3, bo, bo, bo, nullptr, nullptr, nullptr, (float*)d_out,
        M, DMODEL, DMODEL, 0, L, 0, 1.0f);
}

// round 14
// speedup vs baseline: 1.1647x; 1.0605x over previous
#include <cuda_runtime.h>
#include <cuda_fp16.h>
#include <stdint.h>

#define H_ 8
#define DMODEL 512
#define DK_ 64
#define NB 4
#define LMAX 2048

// ---------------- scratch (fp16) ----------------
__device__ __half g_qh[NB * LMAX * DMODEL];
__device__ __half g_kh[NB * LMAX * DMODEL];
__device__ __half g_vh[NB * LMAX * DMODEL];
__device__ __half g_q[NB * LMAX * DMODEL];    // Q pre-scaled by log2e/8
__device__ __half g_k[NB * LMAX * DMODEL];
__device__ __half g_v[NB * LMAX * DMODEL];    // V TRANSPOSED [(b*512+d)][tok]
__device__ __half g_o[NB * LMAX * DMODEL];
__device__ __half g_w[4 * DMODEL * DMODEL];

// ---------------- helpers ----------------
__device__ __forceinline__ void mma_f16(float* d, const unsigned* a, unsigned b0, unsigned b1) {
    asm volatile(
        "mma.sync.aligned.m16n8k16.row.col.f32.f16.f16.f32 "
        "{%0,%1,%2,%3},{%4,%5,%6,%7},{%8,%9},{%0,%1,%2,%3};"
        : "+f"(d[0]), "+f"(d[1]), "+f"(d[2]), "+f"(d[3])
        : "r"(a[0]), "r"(a[1]), "r"(a[2]), "r"(a[3]), "r"(b0), "r"(b1));
}
__device__ __forceinline__ void ldsm4(unsigned& r0, unsigned& r1, unsigned& r2, unsigned& r3,
                                      uint32_t addr) {
    asm volatile("ldmatrix.sync.aligned.m8n8.x4.shared.b16 {%0,%1,%2,%3}, [%4];"
                 : "=r"(r0), "=r"(r1), "=r"(r2), "=r"(r3) : "r"(addr));
}
__device__ __forceinline__ void cp16(uint32_t dst, const void* src) {
    asm volatile("cp.async.cg.shared.global [%0], [%1], 16;" :: "r"(dst), "l"(src));
}
__device__ __forceinline__ unsigned pack_h2(float a, float b) {
    __half2 h = __floats2half2_rn(a, b);
    return *(unsigned*)&h;
}
__device__ __forceinline__ unsigned ex2_h2(unsigned x) {
    unsigned r;
    asm("ex2.approx.f16x2 %0, %1;" : "=r"(r) : "r"(x));
    return r;
}
__device__ __forceinline__ unsigned hmul2(unsigned a, unsigned b) {
    unsigned r;
    asm("mul.f16x2 %0, %1, %2;" : "=r"(r) : "r"(a), "r"(b));
    return r;
}
#define CP_COMMIT asm volatile("cp.async.commit_group;")
#define CP_WAIT1  asm volatile("cp.async.wait_group 1;")
#define CP_WAIT0  asm volatile("cp.async.wait_group 0;")

// ================= merged prepass: fp32 -> fp16 (inputs + weights) ========
__global__ void __launch_bounds__(256) cvt_all(
    const float* __restrict__ s0, const float* __restrict__ s1, const float* __restrict__ s2,
    const float* __restrict__ w0, const float* __restrict__ w1,
    const float* __restrict__ w2, const float* __restrict__ w3,
    __half* __restrict__ d0, __half* __restrict__ d1, __half* __restrict__ d2,
    __half* __restrict__ dw, int n4_in, int n4_w)
{
    const int z = blockIdx.z;
    const float4* s;
    uint2* d;
    int n4;
    if (z < 3) {
        s  = (const float4*)((z == 0) ? s0 : (z == 1) ? s1 : s2);
        d  = (uint2*)((z == 0) ? d0 : (z == 1) ? d1 : d2);
        n4 = n4_in;
    } else {
        const int zw = z - 3;
        s  = (const float4*)((zw == 0) ? w0 : (zw == 1) ? w1 : (zw == 2) ? w2 : w3);
        d  = (uint2*)(dw + (size_t)zw * DMODEL * DMODEL);
        n4 = n4_w;
    }
    for (int i = blockIdx.x * 256 + threadIdx.x; i < n4; i += gridDim.x * 256) {
        float4 v = s[i];
        d[i] = make_uint2(pack_h2(v.x, v.y), pack_h2(v.z, v.w));
    }
}

// ================= fp16 NT GEMM (fused 3-way), 3-stage, k-tile 64 =========
#define GSTG3 32768

__global__ void __launch_bounds__(256, 2) gemm3_f16(
    const __half* __restrict__ A0, const __half* __restrict__ A1, const __half* __restrict__ A2,
    const __half* __restrict__ Wt, int w_off,
    const float* __restrict__ B0, const float* __restrict__ B1, const float* __restrict__ B2,
    __half* __restrict__ C0, __half* __restrict__ C1, __half* __restrict__ C2,
    float* __restrict__ Cf,
    int M, int N, int K, int out_f16, int Lpar, int vt_mode, float q_scale)
{
    extern __shared__ char smc[];
    const uint32_t smb = (uint32_t)__cvta_generic_to_shared(smc);

    const int z = blockIdx.z;
    const __half* A    = (z == 0) ? A0 : (z == 1) ? A1 : A2;
    const __half* W    = Wt + (size_t)(w_off + z) * DMODEL * DMODEL;
    const float*  bias = (z == 0) ? B0 : (z == 1) ? B1 : B2;
    __half*       Ch   = (z == 0) ? C0 : (z == 1) ? C1 : C2;
    const bool    vt   = (z == 2) && vt_mode;
    const float   osc  = (z == 0) ? q_scale : 1.0f;

    const int tid  = threadIdx.x;
    const int lane = tid & 31;
    const int warp = tid >> 5;
    const int g = lane >> 2;
    const int t = lane & 3;
    const int wm = warp >> 1;
    const int wn = warp & 1;
    const int m0 = blockIdx.y * 128;
    const int n0 = blockIdx.x * 128;

    const int grow = tid >> 1;
    const int cb0  = (tid & 1) * 4;
    const __half* Ap = A + (size_t)(m0 + grow) * K;
    const __half* Wp = W + (size_t)(n0 + grow) * K;
    const int xr = grow & 7;
    const uint32_t arow = smb + grow * 128;
    const uint32_t brow = smb + 16384 + grow * 128;

    const int frow = lane & 15;
    const int fhi  = lane >> 4;
    const int fx   = lane & 7;
    int cbk[4];
#pragma unroll
    for (int ks = 0; ks < 4; ks++) cbk[ks] = ((2 * ks + fhi) ^ fx) * 16;
    uint32_t a_rt[2], b_rt[4];
#pragma unroll
    for (int mt = 0; mt < 2; mt++) a_rt[mt] = (wm * 32 + mt * 16 + frow) * 128;
#pragma unroll
    for (int p = 0; p < 4; p++)    b_rt[p] = 16384 + (wn * 64 + p * 16 + frow) * 128;

    float acc[2][8][4] = {};
    const int nK = K / 64;

#define G_ISSUE(it) do {                                                   \
        const uint32_t so_ = ((it) % 3) * GSTG3;                          \
        const int k0_ = (it) * 64;                                        \
        _Pragma("unroll")                                                  \
        for (int j = 0; j < 4; j++) {                                     \
            const int c_ = cb0 + j;                                       \
            cp16(arow + so_ + ((c_ ^ xr) * 16), Ap + k0_ + c_ * 8);       \
            cp16(brow + so_ + ((c_ ^ xr) * 16), Wp + k0_ + c_ * 8);       \
        }                                                                  \
    } while (0)

    G_ISSUE(0); CP_COMMIT;
    G_ISSUE(1); CP_COMMIT;

    for (int it = 0; it < nK; it++) {
        if (it + 1 < nK) { CP_WAIT1; } else { CP_WAIT0; }
        __syncthreads();

        const uint32_t base = smb + (it % 3) * GSTG3;
#pragma unroll
        for (int ks = 0; ks < 4; ks++) {
            unsigned a[2][4], bf[4][4];
#pragma unroll
            for (int mt = 0; mt < 2; mt++)
                ldsm4(a[mt][0], a[mt][1], a[mt][2], a[mt][3], base + a_rt[mt] + cbk[ks]);
#pragma unroll
            for (int p = 0; p < 4; p++)
                ldsm4(bf[p][0], bf[p][1], bf[p][2], bf[p][3], base + b_rt[p] + cbk[ks]);
#pragma unroll
            for (int mt = 0; mt < 2; mt++)
#pragma unroll
                for (int p = 0; p < 4; p++) {
                    mma_f16(acc[mt][2 * p],     a[mt], bf[p][0], bf[p][2]);
                    mma_f16(acc[mt][2 * p + 1], a[mt], bf[p][1], bf[p][3]);
                }
        }
        if (it + 2 < nK) { G_ISSUE(it + 2); CP_COMMIT; }
    }

#pragma unroll
    for (int mt = 0; mt < 2; mt++) {
        const int row0 = m0 + wm * 32 + mt * 16 + g;
#pragma unroll
        for (int nt = 0; nt < 8; nt++) {
            const int col = n0 + wn * 64 + nt * 8 + 2 * t;
            const float b0 = bias[col], b1 = bias[col + 1];
            const float v00 = (acc[mt][nt][0] + b0) * osc, v01 = (acc[mt][nt][1] + b1) * osc;
            const float v10 = (acc[mt][nt][2] + b0) * osc, v11 = (acc[mt][nt][3] + b1) * osc;
            if (!out_f16) {
                *(float2*)&Cf[(size_t)row0 * N + col]       = make_float2(v00, v01);
                *(float2*)&Cf[(size_t)(row0 + 8) * N + col] = make_float2(v10, v11);
            } else if (vt) {
                const int bI  = row0 / Lpar;
                const int tok = row0 - bI * Lpar;
                __half* base0 = Ch + (size_t)(bI * DMODEL + col) * Lpar;
                __half* base1 = base0 + Lpar;
                base0[tok]     = __float2half_rn(v00);
                base1[tok]     = __float2half_rn(v01);
                base0[tok + 8] = __float2half_rn(v10);
                base1[tok + 8] = __float2half_rn(v11);
            } else {
                *(unsigned*)&Ch[(size_t)row0 * N + col]       = pack_h2(v00, v01);
                *(unsigned*)&Ch[(size_t)(row0 + 8) * N + col] = pack_h2(v10, v11);
            }
        }
    }
}

// ================= flash attention: P stays in registers ==================
// C-fragment of S == A-fragment of PV for m16n8k16 -> no P smem round-trip.
// Bq=128, 8 warps, 3-stage K/V rings, 2 CTAs/SM.
// smem: K[3][8192] | V[3][8192] | msk2[4096] = 53248 B
#define AKS 8192
#define ONES2 0x3C003C00u

__global__ void __launch_bounds__(256, 2) attn_f16(
    const __half* __restrict__ Qb, const __half* __restrict__ Kb,
    const __half* __restrict__ Vt, const int* __restrict__ mask,
    __half* __restrict__ Ob, int L)
{
    extern __shared__ char smc[];
    const uint32_t smb = (uint32_t)__cvta_generic_to_shared(smc);
    unsigned* msk2 = (unsigned*)(smc + 6 * AKS);   // L/2 half2 entries

    const int b  = blockIdx.z;
    const int h  = blockIdx.y;
    const int q0 = blockIdx.x * 128;

    const int tid  = threadIdx.x;
    const int lane = tid & 31;
    const int warp = tid >> 5;
    const int g = lane >> 2;
    const int t = lane & 3;
    const int wr0 = warp * 16;

    // mask -> half2 {1,0} table + "any zero" detection
    int bad = 0;
    {
        const int2* m2 = (const int2*)(mask + (size_t)b * L);
        for (int i = tid; i < L / 2; i += 256) {
            int2 mm = m2[i];
            msk2[i] = (mm.x ? 0x3C00u : 0u) | (mm.y ? 0x3C000000u : 0u);
            bad |= (mm.x == 0) | (mm.y == 0);
        }
    }
    const int use_mask = __syncthreads_or(bad);   // also orders msk2 writes

    // Q fragments (pre-scaled by log2e/8 at projection)
    unsigned qa[4][4];
    {
        const __half* q_r0 = Qb + ((size_t)b * L + q0 + wr0 + g) * DMODEL + h * DK_;
        const __half* q_r1 = q_r0 + 8 * DMODEL;
#pragma unroll
        for (int ks = 0; ks < 4; ks++) {
            qa[ks][0] = *(const unsigned*)&q_r0[16 * ks + 2 * t];
            qa[ks][1] = *(const unsigned*)&q_r1[16 * ks + 2 * t];
            qa[ks][2] = *(const unsigned*)&q_r0[16 * ks + 8 + 2 * t];
            qa[ks][3] = *(const unsigned*)&q_r1[16 * ks + 8 + 2 * t];
        }
    }

    float o[8][4] = {};
    float lacc[4] = {};   // row-sum accumulator via ones-mma

    const int frow = lane & 15;
    const int fhi  = lane >> 4;
    const int fx   = lane & 7;
    uint32_t kvrow[4];
#pragma unroll
    for (int p = 0; p < 4; p++) kvrow[p] = (p * 16 + frow) * 128;
    int cb[4];
#pragma unroll
    for (int ks = 0; ks < 4; ks++) cb[ks] = ((2 * ks + fhi) ^ fx) * 16;

    const int lr = tid >> 2;
    const int c0 = (tid & 3) * 2;

#define A_ISSUE(it) do {                                                         \
        const uint32_t so_ = ((it) % 3) * AKS;                                  \
        const int k0_ = (it) * 64;                                              \
        const __half* kp_ = Kb + ((size_t)b * L + k0_ + lr) * DMODEL + h * DK_; \
        const __half* vp_ = Vt + ((size_t)(b * DMODEL + h * DK_ + lr)) * L + k0_;\
        const uint32_t kd_ = smb + so_ + lr * 128;                              \
        const uint32_t vd_ = smb + 3 * AKS + so_ + lr * 128;                    \
        const int xw_ = lr & 7;                                                 \
        _Pragma("unroll")                                                        \
        for (int j = 0; j < 2; j++) {                                           \
            const int c_ = c0 + j;                                              \
            cp16(kd_ + ((c_ ^ xw_) * 16), kp_ + c_ * 8);                        \
            cp16(vd_ + ((c_ ^ xw_) * 16), vp_ + c_ * 8);                        \
        }                                                                        \
    } while (0)

    const int nT = L / 64;
    A_ISSUE(0); CP_COMMIT;
    A_ISSUE(1); CP_COMMIT;

    for (int it = 0; it < nT; it++) {
        if (it + 1 < nT) { CP_WAIT1; } else { CP_WAIT0; }
        __syncthreads();

        const uint32_t smK = smb + (it % 3) * AKS;
        const uint32_t smV = smb + 3 * AKS + (it % 3) * AKS;
        const int k0 = it * 64;

        // ---- S = Q K^T (pre-scaled; exp2 domain) ----
        float s[8][4];
#pragma unroll
        for (int nt = 0; nt < 8; nt++) s[nt][0] = s[nt][1] = s[nt][2] = s[nt][3] = 0.f;
#pragma unroll
        for (int ks = 0; ks < 4; ks++) {
            unsigned kf[4][4];
#pragma unroll
            for (int p = 0; p < 4; p++)
                ldsm4(kf[p][0], kf[p][1], kf[p][2], kf[p][3], smK + kvrow[p] + cb[ks]);
#pragma unroll
            for (int p = 0; p < 4; p++) {
                mma_f16(s[2 * p],     qa[ks], kf[p][0], kf[p][2]);
                mma_f16(s[2 * p + 1], qa[ks], kf[p][1], kf[p][3]);
            }
        }

        // ---- P = [mask *] exp2_h2(S), kept in registers (A-frag layout) ----
        unsigned pp[8][2];
#pragma unroll
        for (int nt = 0; nt < 8; nt++) {
            unsigned lo = ex2_h2(pack_h2(s[nt][0], s[nt][1]));   // rows g
            unsigned hi = ex2_h2(pack_h2(s[nt][2], s[nt][3]));   // rows g+8
            if (use_mask) {
                const unsigned mk = msk2[(k0 + nt * 8) / 2 + t];
                lo = hmul2(lo, mk);
                hi = hmul2(hi, mk);
            }
            pp[nt][0] = lo;
            pp[nt][1] = hi;
        }

        // ---- O += P @ V ; l += P @ 1 (pa taken straight from registers) ----
#pragma unroll
        for (int ks = 0; ks < 4; ks++) {
            unsigned pa[4];
            pa[0] = pp[2 * ks][0];
            pa[1] = pp[2 * ks][1];
            pa[2] = pp[2 * ks + 1][0];
            pa[3] = pp[2 * ks + 1][1];
            unsigned vf[4][4];
#pragma unroll
            for (int p = 0; p < 4; p++)
                ldsm4(vf[p][0], vf[p][1], vf[p][2], vf[p][3], smV + kvrow[p] + cb[ks]);
#pragma unroll
            for (int p = 0; p < 4; p++) {
                mma_f16(o[2 * p],     pa, vf[p][0], vf[p][2]);
                mma_f16(o[2 * p + 1], pa, vf[p][1], vf[p][3]);
            }
            mma_f16(lacc, pa, ONES2, ONES2);
        }
        if (it + 2 < nT) { A_ISSUE(it + 2); CP_COMMIT; }
    }

    const float inv0 = 1.f / lacc[0];
    const float inv1 = 1.f / lacc[2];
    __half* o_r0 = Ob + ((size_t)b * L + q0 + wr0 + g) * DMODEL + h * DK_;
    __half* o_r1 = o_r0 + 8 * DMODEL;
#pragma unroll
    for (int dt = 0; dt < 8; dt++) {
        *(unsigned*)&o_r0[dt * 8 + 2 * t] = pack_h2(o[dt][0] * inv0, o[dt][1] * inv0);
        *(unsigned*)&o_r1[dt * 8 + 2 * t] = pack_h2(o[dt][2] * inv1, o[dt][3] * inv1);
    }
}

// ---------------- launch ----------------
extern "C" void kernel_launch(void* const* d_in, const int* in_sizes, int n_in,
                              void* d_out, int out_size)
{
    const float* query = (const float*)d_in[0];
    const float* key   = (const float*)d_in[1];
    const float* value = (const float*)d_in[2];
    const int*   mask  = (const int*)d_in[3];
    const float* Wq = (const float*)d_in[4];
    const float* bq = (const float*)d_in[5];
    const float* Wk = (const float*)d_in[6];
    const float* bk = (const float*)d_in[7];
    const float* Wv = (const float*)d_in[8];
    const float* bv = (const float*)d_in[9];
    const float* Wo = (const float*)d_in[10];
    const float* bo = (const float*)d_in[11];

    const int N = NB;
    const int L = in_sizes[3] / N;
    const int M = N * L;

    __half *qh, *kh, *vh, *qb, *kb, *vb, *ob, *wb;
    cudaGetSymbolAddress((void**)&qh, g_qh);
    cudaGetSymbolAddress((void**)&kh, g_kh);
    cudaGetSymbolAddress((void**)&vh, g_vh);
    cudaGetSymbolAddress((void**)&qb, g_q);
    cudaGetSymbolAddress((void**)&kb, g_k);
    cudaGetSymbolAddress((void**)&vb, g_v);
    cudaGetSymbolAddress((void**)&ob, g_o);
    cudaGetSymbolAddress((void**)&wb, g_w);

    const int n4_in = M * DMODEL / 4;
    const int n4_w  = DMODEL * DMODEL / 4;
    cvt_all<<<dim3(512, 1, 7), 256>>>(query, key, value, Wq, Wk, Wv, Wo,
                                      qh, kh, vh, wb, n4_in, n4_w);

    const int gemm_smem = 3 * GSTG3;   // 98304 B
    cudaFuncSetAttribute(gemm3_f16, cudaFuncAttributeMaxDynamicSharedMemorySize, gemm_smem);

    const float SC = 0.18033688f;   // (1/sqrt(64)) * log2(e) folded into Q
    gemm3_f16<<<dim3(DMODEL / 128, M / 128, 3), 256, gemm_smem>>>(
        qh, kh, vh, wb, 0, bq, bk, bv, qb, kb, vb, nullptr,
        M, DMODEL, DMODEL, 1, L, 1, SC);

    const int attn_smem = 6 * AKS + 4096;   // 53248 B
    cudaFuncSetAttribute(attn_f16, cudaFuncAttributeMaxDynamicSharedMemorySize, attn_smem);
    attn_f16<<<dim3(L / 128, H_, N), 256, attn_smem>>>(qb, kb, vb, mask, ob, L);

    gemm3_f16<<<dim3(DMODEL / 128, M / 128, 1), 256, gemm_smem>>>(
        ob, ob, ob, wb, 3, bo, bo, bo, nullptr, nullptr, nullptr, (float*)d_out,
        M, DMODEL, DMODEL, 0, L, 0, 1.0f);
}